// round 5
// baseline (speedup 1.0000x reference)
#include <cuda_runtime.h>
#include <math.h>

// Shapes (fixed by the problem)
#define BSZ   8
#define CIN   64
#define HID   128
#define HH    128
#define WW    128
#define NPIX  (HH*WW)          // 16384
#define PH    64               // prior H/W
#define PRIOR_ELEMS (BSZ*NPIX) // 131072

// Scratch (device globals: allocation-free)
__device__ float g_prior[BSZ*NPIX];              // 0.5 MB
__device__ float g_xproj[BSZ*HID*NPIX];          // 67 MB
__device__ float g_Abar [BSZ*HID*NPIX];          // 67 MB
__device__ float g_b    [BSZ*HID*NPIX];          // 67 MB
__device__ float g_scan [BSZ*HID*NPIX];          // 67 MB

// ---------------------------------------------------------------------------
// Kernel 1: bilinear upsample (align_corners=True) 64x64 -> 128x128, clamp,
// write to scratch AND to the tail of d_out (second tuple output).
// ---------------------------------------------------------------------------
__global__ void k_prior_up(const float* __restrict__ prior, float* __restrict__ out_prior)
{
    int n = blockIdx.x * blockDim.x + threadIdx.x;
    if (n >= BSZ*NPIX) return;
    int b = n >> 14;
    int p = n & (NPIX-1);
    int h = p >> 7;
    int w = p & 127;

    double yfd = (double)h * 63.0 / 127.0;
    double xfd = (double)w * 63.0 / 127.0;
    int y0 = (int)floor(yfd); int y1 = min(y0+1, PH-1);
    int x0 = (int)floor(xfd); int x1 = min(x0+1, PH-1);
    float wy = (float)(yfd - y0);
    float wx = (float)(xfd - x0);

    const float* img = prior + b*PH*PH;
    float v00 = img[y0*PH + x0], v01 = img[y0*PH + x1];
    float v10 = img[y1*PH + x0], v11 = img[y1*PH + x1];
    float r0 = v00*(1.f-wy) + v10*wy;
    float r1 = v01*(1.f-wy) + v11*wy;
    float v  = r0*(1.f-wx) + r1*wx;
    v = fminf(fmaxf(v, -1.f), 1.f);
    g_prior[n]    = v;
    out_prior[n]  = v;
}

// ---------------------------------------------------------------------------
// Kernel 2: x_proj = W_in @ x + b_in      [B,HID,NPIX]   (guarded)
// ---------------------------------------------------------------------------
__global__ void k_xproj(const float* __restrict__ x,
                        const float* __restrict__ Wi,
                        const float* __restrict__ bi,
                        const float* __restrict__ gammap)
{
    if (gammap[0] == 0.0f) return;
    __shared__ float sW[HID*CIN];   // 32 KB
    __shared__ float sx[CIN][32];   // 8 KB
    int b  = blockIdx.y;
    int p0 = blockIdx.x * 32;

    for (int i = threadIdx.x; i < HID*CIN; i += 256) sW[i] = Wi[i];
    for (int i = threadIdx.x; i < CIN*32;  i += 256) {
        int c = i >> 5, p = i & 31;
        sx[c][p] = x[(((long)b*CIN + c) << 14) + p0 + p];
    }
    __syncthreads();

    int p   = threadIdx.x & 31;
    int ocb = (threadIdx.x >> 5) * 16;
    #pragma unroll 1
    for (int oc = ocb; oc < ocb + 16; ++oc) {
        float s = bi[oc];
        #pragma unroll
        for (int c = 0; c < CIN; ++c) s += sW[oc*CIN + c] * sx[c][p];
        g_xproj[(((long)b*HID + oc) << 14) + p0 + p] = s;
    }
}

// ---------------------------------------------------------------------------
// Kernel 3: delta/B_k/A_bar/b     (guarded)
//   delta = softplus(W_delta@xp + b_delta + lambda*prior)
//   Bk    = (W_B@xp + b_B) * (1 + alpha*prior)
//   A_bar = exp(delta * -exp(A[oc]));   b = delta*Bk*xp[oc]
// ---------------------------------------------------------------------------
__global__ void k_gates(const float* __restrict__ Wd, const float* __restrict__ bd,
                        const float* __restrict__ Wb, const float* __restrict__ bb_,
                        const float* __restrict__ lamp, const float* __restrict__ alpp,
                        const float* __restrict__ Aarr, const float* __restrict__ gammap)
{
    if (gammap[0] == 0.0f) return;
    __shared__ float sxp[HID*33];   // ~16.9 KB
    int b  = blockIdx.y;
    int p0 = blockIdx.x * 32;

    for (int i = threadIdx.x; i < HID*32; i += 256) {
        int c = i >> 5, p = i & 31;
        sxp[c*33 + p] = g_xproj[(((long)b*HID + c) << 14) + p0 + p];
    }
    __syncthreads();

    int p   = threadIdx.x & 31;
    int ocb = (threadIdx.x >> 5) * 16;
    float pr  = g_prior[b*NPIX + p0 + p];
    float lam = lamp[0], alp = alpp[0];
    float m1  = 1.f + alp*pr;

    #pragma unroll 1
    for (int oc = ocb; oc < ocb + 16; ++oc) {
        float ds = bd[oc], bs = bb_[oc];
        #pragma unroll
        for (int c = 0; c < HID; ++c) {
            float xp = sxp[c*33 + p];
            ds += Wd[oc*HID + c] * xp;
            bs += Wb[oc*HID + c] * xp;
        }
        float dpre  = ds + lam*pr;
        // stable softplus matching jax.nn.softplus
        float delta = fmaxf(dpre, 0.f) + log1pf(expf(-fabsf(dpre)));
        float Bk    = bs * m1;
        float An    = -expf(Aarr[oc]);
        long  idx   = (((long)b*HID + oc) << 14) + p0 + p;
        g_Abar[idx] = expf(delta * An);
        g_b[idx]    = delta * Bk * sxp[oc*33 + p];
    }
}

// warp-level inclusive scan helpers (per 4-element chunks per lane)
__device__ __forceinline__ void scan_row(float a0,float a1,float a2,float a3,
                                         float b0,float b1,float b2,float b3,
                                         int lane,
                                         float&h0,float&h1,float&h2,float&h3)
{
    // local prefix products
    float q0=a0, q1=q0*a1, q2=q1*a2, q3=q2*a3;
    float v = q3;
    #pragma unroll
    for (int d=1; d<32; d<<=1) { float t=__shfl_up_sync(0xffffffffu, v, d); if (lane>=d) v*=t; }
    float ep = __shfl_up_sync(0xffffffffu, v, 1); if (lane==0) ep = 1.f;
    float P0=ep*q0, P1=ep*q1, P2=ep*q2, P3=ep*q3;
    float s0=b0/fmaxf(P0,1e-8f), s1=b1/fmaxf(P1,1e-8f);
    float s2=b2/fmaxf(P2,1e-8f), s3=b3/fmaxf(P3,1e-8f);
    float t0=s0, t1=t0+s1, t2=t1+s2, t3=t2+s3;
    float w = t3;
    #pragma unroll
    for (int d=1; d<32; d<<=1) { float t=__shfl_up_sync(0xffffffffu, w, d); if (lane>=d) w+=t; }
    float es = __shfl_up_sync(0xffffffffu, w, 1); if (lane==0) es = 0.f;
    h0 = P0*(es+t0); h1 = P1*(es+t1); h2 = P2*(es+t2); h3 = P3*(es+t3);
}

// ---------------------------------------------------------------------------
// Kernel 4: horizontal scan (axis=W). One warp per row.   (guarded)
// ---------------------------------------------------------------------------
__global__ void k_scan_h(const float* __restrict__ gammap)
{
    if (gammap[0] == 0.0f) return;
    int gwarp = (blockIdx.x * blockDim.x + threadIdx.x) >> 5;
    int lane  = threadIdx.x & 31;
    if (gwarp >= BSZ*HID*HH) return;
    long base = (long)gwarp * WW;
    float4 a = reinterpret_cast<const float4*>(g_Abar + base)[lane];
    float4 b = reinterpret_cast<const float4*>(g_b    + base)[lane];
    float h0,h1,h2,h3;
    scan_row(a.x,a.y,a.z,a.w, b.x,b.y,b.z,b.w, lane, h0,h1,h2,h3);
    reinterpret_cast<float4*>(g_scan + base)[lane] = make_float4(h0,h1,h2,h3);
}

// ---------------------------------------------------------------------------
// Kernel 5: vertical scan (axis=H), accumulate into g_scan.   (guarded)
// block = one (b,channel) image x 32-column tile; 8 warps scan 4 cols each
// ---------------------------------------------------------------------------
__global__ void k_scan_v(const float* __restrict__ gammap)
{
    if (gammap[0] == 0.0f) return;
    __shared__ float sA[HH*33];
    __shared__ float sB[HH*33];
    int img  = blockIdx.y;              // 0..BSZ*HID-1
    int col0 = blockIdx.x * 32;
    long base = (long)img * NPIX;

    for (int i = threadIdx.x; i < HH*32; i += 256) {
        int r = i >> 5, c = i & 31;
        sA[r*33 + c] = g_Abar[base + r*WW + col0 + c];
        sB[r*33 + c] = g_b   [base + r*WW + col0 + c];
    }
    __syncthreads();

    int warp = threadIdx.x >> 5;
    int lane = threadIdx.x & 31;
    #pragma unroll 1
    for (int cc = 0; cc < 4; ++cc) {
        int col = warp*4 + cc;
        int r0  = lane*4;
        float a0=sA[(r0+0)*33+col], a1=sA[(r0+1)*33+col], a2=sA[(r0+2)*33+col], a3=sA[(r0+3)*33+col];
        float b0=sB[(r0+0)*33+col], b1=sB[(r0+1)*33+col], b2=sB[(r0+2)*33+col], b3=sB[(r0+3)*33+col];
        float h0,h1,h2,h3;
        scan_row(a0,a1,a2,a3, b0,b1,b2,b3, lane, h0,h1,h2,h3);
        g_scan[base + (r0+0)*WW + col0 + col] += h0;
        g_scan[base + (r0+1)*WW + col0 + col] += h1;
        g_scan[base + (r0+2)*WW + col0 + col] += h2;
        g_scan[base + (r0+3)*WW + col0 + col] += h3;
    }
}

// ---------------------------------------------------------------------------
// Kernel 6: out = x + gamma*(W_out@(scan_h+scan_v) + b_out)
// gamma==0 fast path: pure float4 copy of x -> y.
// ---------------------------------------------------------------------------
__global__ void k_final(const float* __restrict__ x,
                        const float* __restrict__ Wout,
                        const float* __restrict__ bout,
                        const float* __restrict__ gammap,
                        float* __restrict__ y)
{
    int b  = blockIdx.y;
    int p0 = blockIdx.x * 32;
    float gamma = gammap[0];

    if (gamma == 0.0f) {
        // copy x[b, :, p0:p0+32]  (CIN*8 float4 = 512 f4, 256 threads)
        const float4* xs = reinterpret_cast<const float4*>(x);
        float4*       ys = reinterpret_cast<float4*>(y);
        #pragma unroll
        for (int k = 0; k < 2; ++k) {
            int i = k*256 + threadIdx.x;       // 0..511
            int c = i >> 3, v = i & 7;
            long idx = ((((long)b*CIN + c) << 14) + p0) / 4 + v;
            ys[idx] = xs[idx];
        }
        return;
    }

    __shared__ float sS[HID*33];
    for (int i = threadIdx.x; i < HID*32; i += 256) {
        int c = i >> 5, p = i & 31;
        sS[c*33 + p] = g_scan[(((long)b*HID + c) << 14) + p0 + p];
    }
    __syncthreads();

    int p   = threadIdx.x & 31;
    int ocb = (threadIdx.x >> 5) * 8;
    #pragma unroll 1
    for (int oc = ocb; oc < ocb + 8; ++oc) {
        float acc = bout[oc];
        #pragma unroll
        for (int c = 0; c < HID; ++c) acc += Wout[oc*HID + c] * sS[c*33 + p];
        long idx = (((long)b*CIN + oc) << 14) + p0 + p;
        y[idx] = x[idx] + gamma * acc;
    }
}

// ---------------------------------------------------------------------------
extern "C" void kernel_launch(void* const* d_in, const int* in_sizes, int n_in,
                              void* d_out, int out_size)
{
    const float* x      = (const float*)d_in[0];
    const float* prior  = (const float*)d_in[1];
    const float* W_in   = (const float*)d_in[2];
    const float* b_in   = (const float*)d_in[3];
    const float* W_out  = (const float*)d_in[4];
    const float* b_out  = (const float*)d_in[5];
    const float* W_del  = (const float*)d_in[6];
    const float* b_del  = (const float*)d_in[7];
    const float* W_B    = (const float*)d_in[8];
    const float* b_B    = (const float*)d_in[9];
    const float* lam    = (const float*)d_in[10];
    const float* alp    = (const float*)d_in[11];
    const float* A      = (const float*)d_in[12];
    const float* gamma  = (const float*)d_in[13];

    float* y         = (float*)d_out;
    float* out_prior = (float*)d_out + (out_size - PRIOR_ELEMS);

    // second tuple output (always needed)
    k_prior_up<<<(BSZ*NPIX + 255)/256, 256>>>(prior, out_prior);

    // heavy path (device-side early-exit when gamma == 0)
    k_xproj <<<dim3(NPIX/32, BSZ), 256>>>(x, W_in, b_in, gamma);
    k_gates <<<dim3(NPIX/32, BSZ), 256>>>(W_del, b_del, W_B, b_B, lam, alp, A, gamma);
    k_scan_h<<<(BSZ*HID*HH*32)/256, 256>>>(gamma);
    k_scan_v<<<dim3(WW/32, BSZ*HID), 256>>>(gamma);

    // first tuple output (copy fast-path when gamma == 0)
    k_final <<<dim3(NPIX/32, BSZ), 256>>>(x, W_out, b_out, gamma, y);
}

// round 6
// speedup vs baseline: 2.0579x; 2.0579x over previous
#include <cuda_runtime.h>
#include <math.h>

// Shapes (fixed by the problem)
#define BSZ   8
#define CIN   64
#define HID   128
#define HH    128
#define WW    128
#define NPIX  (HH*WW)          // 16384
#define PH    64               // prior H/W
#define PRIOR_ELEMS (BSZ*NPIX) // 131072

// Scratch (device globals: allocation-free)
__device__ float g_prior[BSZ*NPIX];              // 0.5 MB
__device__ float g_xproj[BSZ*HID*NPIX];          // 67 MB
__device__ float g_Abar [BSZ*HID*NPIX];          // 67 MB
__device__ float g_b    [BSZ*HID*NPIX];          // 67 MB
__device__ float g_scan [BSZ*HID*NPIX];          // 67 MB

// ---------------------------------------------------------------------------
// Kernel A (unguarded): fused
//   blocks [0, 2048):    gamma==0 fast-path copy x -> y (float4, coalesced)
//   blocks [2048, 2560): bilinear upsample 64->128 (align_corners) + clamp,
//                        write to g_prior AND out_prior (always needed)
// When gamma != 0 the copy blocks exit; guarded k_final later writes all of y.
// ---------------------------------------------------------------------------
#define COPY_BLOCKS 2048
__global__ void k_prior_copy(const float* __restrict__ prior,
                             const float* __restrict__ x,
                             const float* __restrict__ gammap,
                             float* __restrict__ y,
                             float* __restrict__ out_prior)
{
    if (blockIdx.x < COPY_BLOCKS) {
        if (gammap[0] != 0.0f) return;
        // 2,097,152 float4 total; 1024 per block, 4 per thread, coalesced
        const float4* xs = reinterpret_cast<const float4*>(x);
        float4*       ys = reinterpret_cast<float4*>(y);
        long base = (long)blockIdx.x * 1024 + threadIdx.x;
        #pragma unroll
        for (int k = 0; k < 4; ++k)
            ys[base + k*256] = xs[base + k*256];
        return;
    }

    int n = (blockIdx.x - COPY_BLOCKS) * 256 + threadIdx.x;   // 0..131071
    int b = n >> 14;
    int p = n & (NPIX-1);
    int h = p >> 7;
    int w = p & 127;

    double yfd = (double)h * 63.0 / 127.0;
    double xfd = (double)w * 63.0 / 127.0;
    int y0 = (int)floor(yfd); int y1 = min(y0+1, PH-1);
    int x0 = (int)floor(xfd); int x1 = min(x0+1, PH-1);
    float wy = (float)(yfd - y0);
    float wx = (float)(xfd - x0);

    const float* img = prior + b*PH*PH;
    float v00 = img[y0*PH + x0], v01 = img[y0*PH + x1];
    float v10 = img[y1*PH + x0], v11 = img[y1*PH + x1];
    float r0 = v00*(1.f-wy) + v10*wy;
    float r1 = v01*(1.f-wy) + v11*wy;
    float v  = r0*(1.f-wx) + r1*wx;
    v = fminf(fmaxf(v, -1.f), 1.f);
    g_prior[n]   = v;
    out_prior[n] = v;
}

// ---------------------------------------------------------------------------
// Kernel 2 (guarded, grid-stride): x_proj = W_in @ x + b_in
// virtual tiles: 4096 = 8 batches x 512 pixel-tiles of 32
// ---------------------------------------------------------------------------
__global__ void k_xproj(const float* __restrict__ x,
                        const float* __restrict__ Wi,
                        const float* __restrict__ bi,
                        const float* __restrict__ gammap)
{
    if (gammap[0] == 0.0f) return;
    __shared__ float sW[HID*CIN];   // 32 KB
    __shared__ float sx[CIN][32];   // 8 KB
    for (int i = threadIdx.x; i < HID*CIN; i += 256) sW[i] = Wi[i];

    for (int t = blockIdx.x; t < BSZ*512; t += gridDim.x) {
        int b  = t >> 9;
        int p0 = (t & 511) * 32;
        __syncthreads();
        for (int i = threadIdx.x; i < CIN*32; i += 256) {
            int c = i >> 5, p = i & 31;
            sx[c][p] = x[(((long)b*CIN + c) << 14) + p0 + p];
        }
        __syncthreads();

        int p   = threadIdx.x & 31;
        int ocb = (threadIdx.x >> 5) * 16;
        #pragma unroll 1
        for (int oc = ocb; oc < ocb + 16; ++oc) {
            float s = bi[oc];
            #pragma unroll
            for (int c = 0; c < CIN; ++c) s += sW[oc*CIN + c] * sx[c][p];
            g_xproj[(((long)b*HID + oc) << 14) + p0 + p] = s;
        }
    }
}

// ---------------------------------------------------------------------------
// Kernel 3 (guarded, grid-stride): delta/B_k/A_bar/b
// ---------------------------------------------------------------------------
__global__ void k_gates(const float* __restrict__ Wd, const float* __restrict__ bd,
                        const float* __restrict__ Wb, const float* __restrict__ bb_,
                        const float* __restrict__ lamp, const float* __restrict__ alpp,
                        const float* __restrict__ Aarr, const float* __restrict__ gammap)
{
    if (gammap[0] == 0.0f) return;
    __shared__ float sxp[HID*33];   // ~16.9 KB
    float lam = lamp[0], alp = alpp[0];

    for (int t = blockIdx.x; t < BSZ*512; t += gridDim.x) {
        int b  = t >> 9;
        int p0 = (t & 511) * 32;
        __syncthreads();
        for (int i = threadIdx.x; i < HID*32; i += 256) {
            int c = i >> 5, p = i & 31;
            sxp[c*33 + p] = g_xproj[(((long)b*HID + c) << 14) + p0 + p];
        }
        __syncthreads();

        int p   = threadIdx.x & 31;
        int ocb = (threadIdx.x >> 5) * 16;
        float pr = g_prior[b*NPIX + p0 + p];
        float m1 = 1.f + alp*pr;

        #pragma unroll 1
        for (int oc = ocb; oc < ocb + 16; ++oc) {
            float ds = bd[oc], bs = bb_[oc];
            #pragma unroll
            for (int c = 0; c < HID; ++c) {
                float xp = sxp[c*33 + p];
                ds += Wd[oc*HID + c] * xp;
                bs += Wb[oc*HID + c] * xp;
            }
            float dpre  = ds + lam*pr;
            float delta = fmaxf(dpre, 0.f) + log1pf(expf(-fabsf(dpre)));
            float Bk    = bs * m1;
            float An    = -expf(Aarr[oc]);
            long  idx   = (((long)b*HID + oc) << 14) + p0 + p;
            g_Abar[idx] = expf(delta * An);
            g_b[idx]    = delta * Bk * sxp[oc*33 + p];
        }
    }
}

// warp-level inclusive scan (4 elements per lane, 128 per warp)
__device__ __forceinline__ void scan_row(float a0,float a1,float a2,float a3,
                                         float b0,float b1,float b2,float b3,
                                         int lane,
                                         float&h0,float&h1,float&h2,float&h3)
{
    float q0=a0, q1=q0*a1, q2=q1*a2, q3=q2*a3;
    float v = q3;
    #pragma unroll
    for (int d=1; d<32; d<<=1) { float t=__shfl_up_sync(0xffffffffu, v, d); if (lane>=d) v*=t; }
    float ep = __shfl_up_sync(0xffffffffu, v, 1); if (lane==0) ep = 1.f;
    float P0=ep*q0, P1=ep*q1, P2=ep*q2, P3=ep*q3;
    float s0=b0/fmaxf(P0,1e-8f), s1=b1/fmaxf(P1,1e-8f);
    float s2=b2/fmaxf(P2,1e-8f), s3=b3/fmaxf(P3,1e-8f);
    float t0=s0, t1=t0+s1, t2=t1+s2, t3=t2+s3;
    float w = t3;
    #pragma unroll
    for (int d=1; d<32; d<<=1) { float t=__shfl_up_sync(0xffffffffu, w, d); if (lane>=d) w+=t; }
    float es = __shfl_up_sync(0xffffffffu, w, 1); if (lane==0) es = 0.f;
    h0 = P0*(es+t0); h1 = P1*(es+t1); h2 = P2*(es+t2); h3 = P3*(es+t3);
}

// ---------------------------------------------------------------------------
// Kernel 4 (guarded, grid-stride): horizontal scan. One warp per row.
// ---------------------------------------------------------------------------
__global__ void k_scan_h(const float* __restrict__ gammap)
{
    if (gammap[0] == 0.0f) return;
    int warp0 = (blockIdx.x * blockDim.x + threadIdx.x) >> 5;
    int nwarp = (gridDim.x * blockDim.x) >> 5;
    int lane  = threadIdx.x & 31;
    for (int row = warp0; row < BSZ*HID*HH; row += nwarp) {
        long base = (long)row * WW;
        float4 a = reinterpret_cast<const float4*>(g_Abar + base)[lane];
        float4 b = reinterpret_cast<const float4*>(g_b    + base)[lane];
        float h0,h1,h2,h3;
        scan_row(a.x,a.y,a.z,a.w, b.x,b.y,b.z,b.w, lane, h0,h1,h2,h3);
        reinterpret_cast<float4*>(g_scan + base)[lane] = make_float4(h0,h1,h2,h3);
    }
}

// ---------------------------------------------------------------------------
// Kernel 5 (guarded, grid-stride): vertical scan, accumulate into g_scan.
// virtual tiles: 4096 = (BSZ*HID images) x (4 col-tiles of 32)
// ---------------------------------------------------------------------------
__global__ void k_scan_v(const float* __restrict__ gammap)
{
    if (gammap[0] == 0.0f) return;
    __shared__ float sA[HH*33];
    __shared__ float sB[HH*33];
    int warp = threadIdx.x >> 5;
    int lane = threadIdx.x & 31;

    for (int t = blockIdx.x; t < BSZ*HID*4; t += gridDim.x) {
        int img  = t >> 2;
        int col0 = (t & 3) * 32;
        long base = (long)img * NPIX;

        __syncthreads();
        for (int i = threadIdx.x; i < HH*32; i += 256) {
            int r = i >> 5, c = i & 31;
            sA[r*33 + c] = g_Abar[base + r*WW + col0 + c];
            sB[r*33 + c] = g_b   [base + r*WW + col0 + c];
        }
        __syncthreads();

        #pragma unroll 1
        for (int cc = 0; cc < 4; ++cc) {
            int col = warp*4 + cc;
            int r0  = lane*4;
            float a0=sA[(r0+0)*33+col], a1=sA[(r0+1)*33+col], a2=sA[(r0+2)*33+col], a3=sA[(r0+3)*33+col];
            float b0=sB[(r0+0)*33+col], b1=sB[(r0+1)*33+col], b2=sB[(r0+2)*33+col], b3=sB[(r0+3)*33+col];
            float h0,h1,h2,h3;
            scan_row(a0,a1,a2,a3, b0,b1,b2,b3, lane, h0,h1,h2,h3);
            g_scan[base + (r0+0)*WW + col0 + col] += h0;
            g_scan[base + (r0+1)*WW + col0 + col] += h1;
            g_scan[base + (r0+2)*WW + col0 + col] += h2;
            g_scan[base + (r0+3)*WW + col0 + col] += h3;
        }
    }
}

// ---------------------------------------------------------------------------
// Kernel 6 (guarded, grid-stride): y = x + gamma*(W_out@(scan)+b_out)
// (only runs when gamma != 0; gamma==0 output already written by k_prior_copy)
// ---------------------------------------------------------------------------
__global__ void k_final(const float* __restrict__ x,
                        const float* __restrict__ Wout,
                        const float* __restrict__ bout,
                        const float* __restrict__ gammap,
                        float* __restrict__ y)
{
    float gamma = gammap[0];
    if (gamma == 0.0f) return;

    __shared__ float sS[HID*33];
    for (int t = blockIdx.x; t < BSZ*512; t += gridDim.x) {
        int b  = t >> 9;
        int p0 = (t & 511) * 32;
        __syncthreads();
        for (int i = threadIdx.x; i < HID*32; i += 256) {
            int c = i >> 5, p = i & 31;
            sS[c*33 + p] = g_scan[(((long)b*HID + c) << 14) + p0 + p];
        }
        __syncthreads();

        int p   = threadIdx.x & 31;
        int ocb = (threadIdx.x >> 5) * 8;
        #pragma unroll 1
        for (int oc = ocb; oc < ocb + 8; ++oc) {
            float acc = bout[oc];
            #pragma unroll
            for (int c = 0; c < HID; ++c) acc += Wout[oc*HID + c] * sS[c*33 + p];
            long idx = (((long)b*CIN + oc) << 14) + p0 + p;
            y[idx] = x[idx] + gamma * acc;
        }
    }
}

// ---------------------------------------------------------------------------
extern "C" void kernel_launch(void* const* d_in, const int* in_sizes, int n_in,
                              void* d_out, int out_size)
{
    const float* x      = (const float*)d_in[0];
    const float* prior  = (const float*)d_in[1];
    const float* W_in   = (const float*)d_in[2];
    const float* b_in   = (const float*)d_in[3];
    const float* W_out  = (const float*)d_in[4];
    const float* b_out  = (const float*)d_in[5];
    const float* W_del  = (const float*)d_in[6];
    const float* b_del  = (const float*)d_in[7];
    const float* W_B    = (const float*)d_in[8];
    const float* b_B    = (const float*)d_in[9];
    const float* lam    = (const float*)d_in[10];
    const float* alp    = (const float*)d_in[11];
    const float* A      = (const float*)d_in[12];
    const float* gamma  = (const float*)d_in[13];

    float* y         = (float*)d_out;
    float* out_prior = (float*)d_out + (out_size - PRIOR_ELEMS);

    // fused: prior upsample (always) + gamma==0 copy fast path
    k_prior_copy<<<COPY_BLOCKS + 512, 256>>>(prior, x, gamma, y, out_prior);

    // heavy path (device-side early-exit when gamma == 0) — tiny grids,
    // grid-stride loops cover the full work when gamma != 0
    k_xproj <<<512, 256>>>(x, W_in, b_in, gamma);
    k_gates <<<512, 256>>>(W_del, b_del, W_B, b_B, lam, alp, A, gamma);
    k_scan_h<<<512, 256>>>(gamma);
    k_scan_v<<<512, 256>>>(gamma);
    k_final <<<512, 256>>>(x, W_out, b_out, gamma, y);
}

// round 7
// speedup vs baseline: 2.9050x; 1.4117x over previous
#include <cuda_runtime.h>
#include <math.h>

// Shapes (fixed by the problem)
#define BSZ   8
#define CIN   64
#define HID   128
#define HH    128
#define WW    128
#define NPIX  (HH*WW)          // 16384
#define PH    64               // prior H/W
#define PRIOR_ELEMS (BSZ*NPIX) // 131072

#define NBLK  148              // persistent mega-kernel grid (1 CTA/SM resident)

// Scratch (device globals: allocation-free)
__device__ float g_prior[BSZ*NPIX];              // 0.5 MB
__device__ float g_xproj[BSZ*HID*NPIX];          // 67 MB
__device__ float g_Abar [BSZ*HID*NPIX];          // 67 MB
__device__ float g_b    [BSZ*HID*NPIX];          // 67 MB
__device__ float g_scan [BSZ*HID*NPIX];          // 67 MB

// software grid barrier state
__device__ unsigned g_bar_count = 0;
__device__ volatile unsigned g_bar_gen = 0;

__device__ __forceinline__ void grid_barrier()
{
    __syncthreads();
    if (threadIdx.x == 0) {
        unsigned gen = g_bar_gen;
        __threadfence();
        unsigned arrived = atomicInc(&g_bar_count, NBLK - 1); // wraps to 0 at NBLK-1
        if (arrived == NBLK - 1) {
            g_bar_gen = gen + 1;          // release
        } else {
            while (g_bar_gen == gen) { }  // spin (all CTAs resident)
        }
        __threadfence();
    }
    __syncthreads();
}

// ---------------------------------------------------------------------------
// Kernel A (unguarded): fused
//   blocks [0, 2048):    gamma==0 fast-path copy x -> y (float4, coalesced)
//   blocks [2048, 2560): bilinear upsample 64->128 (align_corners) + clamp,
//                        write to g_prior AND out_prior (always needed)
// When gamma != 0 the copy blocks exit; the mega-kernel writes all of y.
// ---------------------------------------------------------------------------
#define COPY_BLOCKS 2048
__global__ void k_prior_copy(const float* __restrict__ prior,
                             const float* __restrict__ x,
                             const float* __restrict__ gammap,
                             float* __restrict__ y,
                             float* __restrict__ out_prior)
{
    if (blockIdx.x < COPY_BLOCKS) {
        if (gammap[0] != 0.0f) return;
        const float4* xs = reinterpret_cast<const float4*>(x);
        float4*       ys = reinterpret_cast<float4*>(y);
        long base = (long)blockIdx.x * 1024 + threadIdx.x;
        #pragma unroll
        for (int k = 0; k < 4; ++k)
            ys[base + k*256] = xs[base + k*256];
        return;
    }

    int n = (blockIdx.x - COPY_BLOCKS) * 256 + threadIdx.x;   // 0..131071
    int b = n >> 14;
    int p = n & (NPIX-1);
    int h = p >> 7;
    int w = p & 127;

    double yfd = (double)h * 63.0 / 127.0;
    double xfd = (double)w * 63.0 / 127.0;
    int y0 = (int)floor(yfd); int y1 = min(y0+1, PH-1);
    int x0 = (int)floor(xfd); int x1 = min(x0+1, PH-1);
    float wy = (float)(yfd - y0);
    float wx = (float)(xfd - x0);

    const float* img = prior + b*PH*PH;
    float v00 = img[y0*PH + x0], v01 = img[y0*PH + x1];
    float v10 = img[y1*PH + x0], v11 = img[y1*PH + x1];
    float r0 = v00*(1.f-wy) + v10*wy;
    float r1 = v01*(1.f-wy) + v11*wy;
    float v  = r0*(1.f-wx) + r1*wx;
    v = fminf(fmaxf(v, -1.f), 1.f);
    g_prior[n]   = v;
    out_prior[n] = v;
}

// warp-level inclusive scan (4 elements per lane, 128 per warp)
__device__ __forceinline__ void scan_row(float a0,float a1,float a2,float a3,
                                         float b0,float b1,float b2,float b3,
                                         int lane,
                                         float&h0,float&h1,float&h2,float&h3)
{
    float q0=a0, q1=q0*a1, q2=q1*a2, q3=q2*a3;
    float v = q3;
    #pragma unroll
    for (int d=1; d<32; d<<=1) { float t=__shfl_up_sync(0xffffffffu, v, d); if (lane>=d) v*=t; }
    float ep = __shfl_up_sync(0xffffffffu, v, 1); if (lane==0) ep = 1.f;
    float P0=ep*q0, P1=ep*q1, P2=ep*q2, P3=ep*q3;
    float s0=b0/fmaxf(P0,1e-8f), s1=b1/fmaxf(P1,1e-8f);
    float s2=b2/fmaxf(P2,1e-8f), s3=b3/fmaxf(P3,1e-8f);
    float t0=s0, t1=t0+s1, t2=t1+s2, t3=t2+s3;
    float w = t3;
    #pragma unroll
    for (int d=1; d<32; d<<=1) { float t=__shfl_up_sync(0xffffffffu, w, d); if (lane>=d) w+=t; }
    float es = __shfl_up_sync(0xffffffffu, w, 1); if (lane==0) es = 0.f;
    h0 = P0*(es+t0); h1 = P1*(es+t1); h2 = P2*(es+t2); h3 = P3*(es+t3);
}

// ---------------------------------------------------------------------------
// Mega-kernel (guarded): the entire heavy path in one launch.
// 148 persistent CTAs, software grid barriers between stages.
// Shared memory is a 40KB union re-used per stage.
// ---------------------------------------------------------------------------
__global__ void __launch_bounds__(256, 1)
k_heavy(const float* __restrict__ x,
        const float* __restrict__ Wi,   const float* __restrict__ bi,
        const float* __restrict__ Wd,   const float* __restrict__ bd,
        const float* __restrict__ Wb,   const float* __restrict__ bb_,
        const float* __restrict__ lamp, const float* __restrict__ alpp,
        const float* __restrict__ Aarr,
        const float* __restrict__ Wout, const float* __restrict__ bout,
        const float* __restrict__ gammap,
        float* __restrict__ y)
{
    float gamma = gammap[0];
    if (gamma == 0.0f) return;

    __shared__ float sbuf[10240];   // 40 KB, aliased per stage

    int warp = threadIdx.x >> 5;
    int lane = threadIdx.x & 31;

    // ---------------- Stage 1: x_proj = W_in @ x + b_in -------------------
    {
        float* sW = sbuf;                       // [HID*CIN] = 8192
        float (*sx)[32] = (float(*)[32])(sbuf + HID*CIN);   // [CIN][32] = 2048
        for (int i = threadIdx.x; i < HID*CIN; i += 256) sW[i] = Wi[i];

        for (int t = blockIdx.x; t < BSZ*512; t += NBLK) {
            int b  = t >> 9;
            int p0 = (t & 511) * 32;
            __syncthreads();
            for (int i = threadIdx.x; i < CIN*32; i += 256) {
                int c = i >> 5, p = i & 31;
                sx[c][p] = x[(((long)b*CIN + c) << 14) + p0 + p];
            }
            __syncthreads();

            int p   = lane;
            int ocb = warp * 16;
            #pragma unroll 1
            for (int oc = ocb; oc < ocb + 16; ++oc) {
                float s = bi[oc];
                #pragma unroll
                for (int c = 0; c < CIN; ++c) s += sW[oc*CIN + c] * sx[c][p];
                g_xproj[(((long)b*HID + oc) << 14) + p0 + p] = s;
            }
        }
    }
    grid_barrier();

    // ---------------- Stage 2: gates -> g_Abar, g_b ------------------------
    {
        float* sxp = sbuf;                      // [HID*33] = 4224
        float lam = lamp[0], alp = alpp[0];

        for (int t = blockIdx.x; t < BSZ*512; t += NBLK) {
            int b  = t >> 9;
            int p0 = (t & 511) * 32;
            __syncthreads();
            for (int i = threadIdx.x; i < HID*32; i += 256) {
                int c = i >> 5, p = i & 31;
                sxp[c*33 + p] = g_xproj[(((long)b*HID + c) << 14) + p0 + p];
            }
            __syncthreads();

            int p   = lane;
            int ocb = warp * 16;
            float pr = g_prior[b*NPIX + p0 + p];
            float m1 = 1.f + alp*pr;

            #pragma unroll 1
            for (int oc = ocb; oc < ocb + 16; ++oc) {
                float ds = bd[oc], bs = bb_[oc];
                #pragma unroll
                for (int c = 0; c < HID; ++c) {
                    float xp = sxp[c*33 + p];
                    ds += Wd[oc*HID + c] * xp;
                    bs += Wb[oc*HID + c] * xp;
                }
                float dpre  = ds + lam*pr;
                float delta = fmaxf(dpre, 0.f) + log1pf(expf(-fabsf(dpre)));
                float Bk    = bs * m1;
                float An    = -expf(Aarr[oc]);
                long  idx   = (((long)b*HID + oc) << 14) + p0 + p;
                g_Abar[idx] = expf(delta * An);
                g_b[idx]    = delta * Bk * sxp[oc*33 + p];
            }
        }
    }
    grid_barrier();

    // ---------------- Stage 3: horizontal scan -----------------------------
    {
        int warp0 = blockIdx.x * 8 + warp;
        for (int row = warp0; row < BSZ*HID*HH; row += NBLK*8) {
            long base = (long)row * WW;
            float4 a = reinterpret_cast<const float4*>(g_Abar + base)[lane];
            float4 b = reinterpret_cast<const float4*>(g_b    + base)[lane];
            float h0,h1,h2,h3;
            scan_row(a.x,a.y,a.z,a.w, b.x,b.y,b.z,b.w, lane, h0,h1,h2,h3);
            reinterpret_cast<float4*>(g_scan + base)[lane] = make_float4(h0,h1,h2,h3);
        }
    }
    grid_barrier();

    // ---------------- Stage 4: vertical scan (accumulate) ------------------
    {
        float* sA = sbuf;                       // [HH*33] = 4224
        float* sB = sbuf + HH*33;               // [HH*33] = 4224

        for (int t = blockIdx.x; t < BSZ*HID*4; t += NBLK) {
            int img  = t >> 2;
            int col0 = (t & 3) * 32;
            long base = (long)img * NPIX;

            __syncthreads();
            for (int i = threadIdx.x; i < HH*32; i += 256) {
                int r = i >> 5, c = i & 31;
                sA[r*33 + c] = g_Abar[base + r*WW + col0 + c];
                sB[r*33 + c] = g_b   [base + r*WW + col0 + c];
            }
            __syncthreads();

            #pragma unroll 1
            for (int cc = 0; cc < 4; ++cc) {
                int col = warp*4 + cc;
                int r0  = lane*4;
                float a0=sA[(r0+0)*33+col], a1=sA[(r0+1)*33+col], a2=sA[(r0+2)*33+col], a3=sA[(r0+3)*33+col];
                float b0=sB[(r0+0)*33+col], b1=sB[(r0+1)*33+col], b2=sB[(r0+2)*33+col], b3=sB[(r0+3)*33+col];
                float h0,h1,h2,h3;
                scan_row(a0,a1,a2,a3, b0,b1,b2,b3, lane, h0,h1,h2,h3);
                g_scan[base + (r0+0)*WW + col0 + col] += h0;
                g_scan[base + (r0+1)*WW + col0 + col] += h1;
                g_scan[base + (r0+2)*WW + col0 + col] += h2;
                g_scan[base + (r0+3)*WW + col0 + col] += h3;
            }
        }
    }
    grid_barrier();

    // ---------------- Stage 5: y = x + gamma*(W_out@scan + b_out) ----------
    {
        float* sS = sbuf;                       // [HID*33] = 4224
        for (int t = blockIdx.x; t < BSZ*512; t += NBLK) {
            int b  = t >> 9;
            int p0 = (t & 511) * 32;
            __syncthreads();
            for (int i = threadIdx.x; i < HID*32; i += 256) {
                int c = i >> 5, p = i & 31;
                sS[c*33 + p] = g_scan[(((long)b*HID + c) << 14) + p0 + p];
            }
            __syncthreads();

            int p   = lane;
            int ocb = warp * 8;
            #pragma unroll 1
            for (int oc = ocb; oc < ocb + 8; ++oc) {
                float acc = bout[oc];
                #pragma unroll
                for (int c = 0; c < HID; ++c) acc += Wout[oc*HID + c] * sS[c*33 + p];
                long idx = (((long)b*CIN + oc) << 14) + p0 + p;
                y[idx] = x[idx] + gamma * acc;
            }
        }
    }
}

// ---------------------------------------------------------------------------
extern "C" void kernel_launch(void* const* d_in, const int* in_sizes, int n_in,
                              void* d_out, int out_size)
{
    const float* x      = (const float*)d_in[0];
    const float* prior  = (const float*)d_in[1];
    const float* W_in   = (const float*)d_in[2];
    const float* b_in   = (const float*)d_in[3];
    const float* W_out  = (const float*)d_in[4];
    const float* b_out  = (const float*)d_in[5];
    const float* W_del  = (const float*)d_in[6];
    const float* b_del  = (const float*)d_in[7];
    const float* W_B    = (const float*)d_in[8];
    const float* b_B    = (const float*)d_in[9];
    const float* lam    = (const float*)d_in[10];
    const float* alp    = (const float*)d_in[11];
    const float* A      = (const float*)d_in[12];
    const float* gamma  = (const float*)d_in[13];

    float* y         = (float*)d_out;
    float* out_prior = (float*)d_out + (out_size - PRIOR_ELEMS);

    // fused: prior upsample (always) + gamma==0 copy fast path
    k_prior_copy<<<COPY_BLOCKS + 512, 256>>>(prior, x, gamma, y, out_prior);

    // entire heavy path in ONE guarded persistent kernel
    k_heavy<<<NBLK, 256>>>(x, W_in, b_in, W_del, b_del, W_B, b_B,
                           lam, alp, A, W_out, b_out, gamma, y);
}